// round 2
// baseline (speedup 1.0000x reference)
#include <cuda_runtime.h>

#define L 2048
#define HID 4096
#define NH 32
#define NKV 8
#define HD 128
#define MAXP 4096

// ---------------- scratch (static device globals; no runtime alloc) --------
__device__ float g_h[(size_t)L * HID];        // rmsnorm output
__device__ float g_q[(size_t)L * HID];        // Q projection (roped in place)
__device__ float g_k[(size_t)L * NKV * HD];   // K projection (roped in place)
__device__ float g_v[(size_t)L * NKV * HD];   // V projection
__device__ float g_attn[(size_t)L * HID];     // attention output

// ---------------- cache copy (out caches = in caches, then scatter) --------
__global__ void copy_caches_kernel(const float4* __restrict__ kin,
                                   const float4* __restrict__ vin,
                                   float4* __restrict__ kout,
                                   float4* __restrict__ vout) {
    int idx = blockIdx.x * 256 + threadIdx.x;
    const int n4 = MAXP * NKV * HD / 4;  // 1048576
    if (idx < n4) {
        kout[idx] = kin[idx];
    } else {
        int j = idx - n4;
        vout[j] = vin[j];
    }
}

// ---------------- RMSNorm: one block per row ----------------
__global__ void __launch_bounds__(256) rmsnorm_kernel(const float* __restrict__ x,
                                                      const float* __restrict__ w) {
    int row = blockIdx.x;
    const float* xr = x + (size_t)row * HID;
    int t = threadIdx.x;
    float vals[16];
    float local = 0.f;
#pragma unroll
    for (int i = 0; i < 16; ++i) {
        float v = xr[t + i * 256];
        vals[i] = v;
        local += v * v;
    }
    __shared__ float red[8];
#pragma unroll
    for (int o = 16; o; o >>= 1) local += __shfl_xor_sync(0xffffffffu, local, o);
    if ((t & 31) == 0) red[t >> 5] = local;
    __syncthreads();
    if (t < 8) {
        float v = red[t];
#pragma unroll
        for (int o = 4; o; o >>= 1) v += __shfl_xor_sync(0xffu, v, o);
        if (t == 0) red[0] = v;
    }
    __syncthreads();
    float rms = rsqrtf(red[0] / (float)HID + 1e-5f);
    float* hr = g_h + (size_t)row * HID;
#pragma unroll
    for (int i = 0; i < 16; ++i) hr[t + i * 256] = vals[i] * rms * w[t + i * 256];
}

// ---------------- GEMM: C[M,N] = A[M,K] @ B[N,K]^T (+res), K=4096 ----------
// 128x128x16 tiles, 256 threads, 8x8 micro-tile.
template <bool ADD_RES>
__global__ void __launch_bounds__(256) gemm_nt_kernel(const float* __restrict__ A,
                                                      const float* __restrict__ B,
                                                      float* __restrict__ C, int N,
                                                      const float* __restrict__ res) {
    __shared__ float Ats[16][128];
    __shared__ float Bts[16][128];
    const int K = HID;
    int bm = blockIdx.y * 128, bn = blockIdx.x * 128;
    int tid = threadIdx.x;
    int tx = tid & 15, ty = tid >> 4;
    float acc[8][8];
#pragma unroll
    for (int i = 0; i < 8; ++i)
#pragma unroll
        for (int j = 0; j < 8; ++j) acc[i][j] = 0.f;

    for (int k0 = 0; k0 < K; k0 += 16) {
#pragma unroll
        for (int l = 0; l < 2; ++l) {
            int i = tid + l * 256;        // 0..511
            int row = i >> 2;             // 0..127
            int c4 = (i & 3) * 4;         // 0,4,8,12
            float4 av = *(const float4*)&A[(size_t)(bm + row) * K + k0 + c4];
            Ats[c4 + 0][row] = av.x; Ats[c4 + 1][row] = av.y;
            Ats[c4 + 2][row] = av.z; Ats[c4 + 3][row] = av.w;
            float4 bv = *(const float4*)&B[(size_t)(bn + row) * K + k0 + c4];
            Bts[c4 + 0][row] = bv.x; Bts[c4 + 1][row] = bv.y;
            Bts[c4 + 2][row] = bv.z; Bts[c4 + 3][row] = bv.w;
        }
        __syncthreads();
#pragma unroll
        for (int kk = 0; kk < 16; ++kk) {
            float4 a0 = *(float4*)&Ats[kk][ty * 8];
            float4 a1 = *(float4*)&Ats[kk][ty * 8 + 4];
            float4 b0 = *(float4*)&Bts[kk][tx * 8];
            float4 b1 = *(float4*)&Bts[kk][tx * 8 + 4];
            float a[8] = {a0.x, a0.y, a0.z, a0.w, a1.x, a1.y, a1.z, a1.w};
            float b[8] = {b0.x, b0.y, b0.z, b0.w, b1.x, b1.y, b1.z, b1.w};
#pragma unroll
            for (int i = 0; i < 8; ++i)
#pragma unroll
                for (int j = 0; j < 8; ++j) acc[i][j] += a[i] * b[j];
        }
        __syncthreads();
    }
#pragma unroll
    for (int i = 0; i < 8; ++i) {
        size_t off = (size_t)(bm + ty * 8 + i) * N + bn + tx * 8;
        float4 c0 = make_float4(acc[i][0], acc[i][1], acc[i][2], acc[i][3]);
        float4 c1 = make_float4(acc[i][4], acc[i][5], acc[i][6], acc[i][7]);
        if (ADD_RES) {
            float4 r0 = *(const float4*)&res[off];
            float4 r1 = *(const float4*)&res[off + 4];
            c0.x += r0.x; c0.y += r0.y; c0.z += r0.z; c0.w += r0.w;
            c1.x += r1.x; c1.y += r1.y; c1.z += r1.z; c1.w += r1.w;
        }
        *(float4*)&C[off] = c0;
        *(float4*)&C[off + 4] = c1;
    }
}

// ---------------- RoPE on Q (in place) ----------------
__global__ void rope_q_kernel(const float* __restrict__ cosb, const float* __restrict__ sinb) {
    int idx = blockIdx.x * 256 + threadIdx.x;  // < L*NH*64
    int d = idx & 63;
    int h = (idx >> 6) & (NH - 1);
    int i = idx >> 11;
    float* qp = g_q + (size_t)i * HID + h * HD;
    float c0 = cosb[i * HD + d], s0 = sinb[i * HD + d];
    float c1 = cosb[i * HD + d + 64], s1 = sinb[i * HD + d + 64];
    float q0 = qp[d], q1 = qp[d + 64];
    qp[d] = q0 * c0 - q1 * s0;
    qp[d + 64] = q1 * c1 + q0 * s1;
}

// ---------------- RoPE on K (in place) + scatter K,V to caches -------------
// position_ids is arange(L) by construction; row index == cache position.
// (Do NOT dereference the position_ids buffer: its dtype is ambiguous
//  (jnp.int64 downcast to int32 under default JAX config) and misreading it
//  as 64-bit was the round-1 illegal-access bug.)
__global__ void rope_kv_kernel(const float* __restrict__ cosb, const float* __restrict__ sinb,
                               float* __restrict__ kc_out, float* __restrict__ vc_out) {
    int idx = blockIdx.x * 256 + threadIdx.x;  // < L*NKV*64
    int d = idx & 63;
    int h = (idx >> 6) & (NKV - 1);
    int i = idx >> 9;
    size_t base = (size_t)i * (NKV * HD) + h * HD;
    float c0 = cosb[i * HD + d], s0 = sinb[i * HD + d];
    float c1 = cosb[i * HD + d + 64], s1 = sinb[i * HD + d + 64];
    float k0 = g_k[base + d], k1 = g_k[base + d + 64];
    float k0n = k0 * c0 - k1 * s0;
    float k1n = k1 * c1 + k0 * s1;
    g_k[base + d] = k0n;
    g_k[base + d + 64] = k1n;
    size_t cb = (size_t)i * (NKV * HD) + h * HD;  // position = i (arange)
    kc_out[cb + d] = k0n;
    kc_out[cb + d + 64] = k1n;
    vc_out[cb + d] = g_v[base + d];
    vc_out[cb + d + 64] = g_v[base + d + 64];
}

// ---------------- Flash attention (causal, GQA g=4), fp32 ------------------
// Block = (q-tile of 64 rows, one q head). BN=64 kv tile, HD=128.
// smem: Qts[128][64], Kts[128][64], Vs[64][128], Ps[64][68]  -> 115712 B
#define PS_STRIDE 68
__global__ void __launch_bounds__(256) flash_kernel(const float* __restrict__ q,
                                                    const float* __restrict__ k,
                                                    const float* __restrict__ v,
                                                    float* __restrict__ o) {
    extern __shared__ float sm[];
    float* Qts = sm;           // [128][64] transposed
    float* Kts = sm + 8192;    // [128][64] transposed
    float* Vs = sm + 16384;    // [64][128]
    float* Ps = sm + 24576;    // [64][PS_STRIDE]
    const int qt = blockIdx.x, head = blockIdx.y;
    const int kvh = head >> 2;
    const int tid = threadIdx.x;
    const int tx = tid & 15, ty = tid >> 4;
    const float scale = 0.08838834764831845f;  // 1/sqrt(128)

    // load Q tile (transposed)
    for (int i = tid; i < 2048; i += 256) {
        int row = i >> 5;
        int c4 = (i & 31) * 4;
        float4 qv = *(const float4*)&q[(size_t)(qt * 64 + row) * HID + head * HD + c4];
        Qts[(c4 + 0) * 64 + row] = qv.x;
        Qts[(c4 + 1) * 64 + row] = qv.y;
        Qts[(c4 + 2) * 64 + row] = qv.z;
        Qts[(c4 + 3) * 64 + row] = qv.w;
    }

    float m_i[4], l_i[4], acc[4][8];
#pragma unroll
    for (int i = 0; i < 4; ++i) {
        m_i[i] = -1e30f;
        l_i[i] = 0.f;
#pragma unroll
        for (int d = 0; d < 8; ++d) acc[i][d] = 0.f;
    }

    for (int kt = 0; kt <= qt; ++kt) {
        __syncthreads();  // previous PV done (and Q load on first iter)
        for (int i = tid; i < 2048; i += 256) {
            int row = i >> 5;
            int c4 = (i & 31) * 4;
            size_t g = (size_t)(kt * 64 + row) * (NKV * HD) + kvh * HD + c4;
            float4 kv4 = *(const float4*)&k[g];
            Kts[(c4 + 0) * 64 + row] = kv4.x;
            Kts[(c4 + 1) * 64 + row] = kv4.y;
            Kts[(c4 + 2) * 64 + row] = kv4.z;
            Kts[(c4 + 3) * 64 + row] = kv4.w;
            *(float4*)&Vs[row * 128 + c4] = *(const float4*)&v[g];
        }
        __syncthreads();

        // S = Q K^T on 4x4 micro-tile
        float s[4][4];
#pragma unroll
        for (int i = 0; i < 4; ++i)
#pragma unroll
            for (int j = 0; j < 4; ++j) s[i][j] = 0.f;

#pragma unroll 8
        for (int d = 0; d < 128; ++d) {
            float4 a4 = *(float4*)&Qts[d * 64 + ty * 4];
            float4 b4 = *(float4*)&Kts[d * 64 + tx * 4];
            float a[4] = {a4.x, a4.y, a4.z, a4.w};
            float b[4] = {b4.x, b4.y, b4.z, b4.w};
#pragma unroll
            for (int i = 0; i < 4; ++i)
#pragma unroll
                for (int j = 0; j < 4; ++j) s[i][j] += a[i] * b[j];
        }

        const bool diag = (kt == qt);
#pragma unroll
        for (int i = 0; i < 4; ++i) {
            int qr = qt * 64 + ty * 4 + i;
            float mt = -1e30f;
#pragma unroll
            for (int j = 0; j < 4; ++j) {
                float sv = s[i][j] * scale;
                if (diag && (kt * 64 + tx * 4 + j) > qr) sv = -1e30f;
                s[i][j] = sv;
                mt = fmaxf(mt, sv);
            }
#pragma unroll
            for (int off = 1; off < 16; off <<= 1)
                mt = fmaxf(mt, __shfl_xor_sync(0xffffffffu, mt, off));
            float mnew = fmaxf(m_i[i], mt);
            float corr = __expf(m_i[i] - mnew);
            m_i[i] = mnew;
            float rs = 0.f;
#pragma unroll
            for (int j = 0; j < 4; ++j) {
                float p = __expf(s[i][j] - mnew);
                Ps[(tx * 4 + j) * PS_STRIDE + ty * 4 + i] = p;  // transposed
                rs += p;
            }
#pragma unroll
            for (int off = 1; off < 16; off <<= 1)
                rs += __shfl_xor_sync(0xffffffffu, rs, off);
            l_i[i] = l_i[i] * corr + rs;
#pragma unroll
            for (int d = 0; d < 8; ++d) acc[i][d] *= corr;
        }
        __syncthreads();

        // O += P @ V, 4x8 micro-tile
#pragma unroll 4
        for (int j = 0; j < 64; ++j) {
            float4 p4 = *(float4*)&Ps[j * PS_STRIDE + ty * 4];
            float4 v0 = *(float4*)&Vs[j * 128 + tx * 8];
            float4 v1 = *(float4*)&Vs[j * 128 + tx * 8 + 4];
            float p[4] = {p4.x, p4.y, p4.z, p4.w};
            float vv[8] = {v0.x, v0.y, v0.z, v0.w, v1.x, v1.y, v1.z, v1.w};
#pragma unroll
            for (int i = 0; i < 4; ++i)
#pragma unroll
                for (int d = 0; d < 8; ++d) acc[i][d] += p[i] * vv[d];
        }
    }

#pragma unroll
    for (int i = 0; i < 4; ++i) {
        float inv = 1.f / l_i[i];
        size_t off = (size_t)(qt * 64 + ty * 4 + i) * HID + head * HD + tx * 8;
        float4 c0 = make_float4(acc[i][0] * inv, acc[i][1] * inv, acc[i][2] * inv, acc[i][3] * inv);
        float4 c1 = make_float4(acc[i][4] * inv, acc[i][5] * inv, acc[i][6] * inv, acc[i][7] * inv);
        *(float4*)&o[off] = c0;
        *(float4*)&o[off + 4] = c1;
    }
}

// ---------------- launch ----------------
extern "C" void kernel_launch(void* const* d_in, const int* in_sizes, int n_in,
                              void* d_out, int out_size) {
    const float* x = (const float*)d_in[0];
    const float* cosb = (const float*)d_in[1];
    const float* sinb = (const float*)d_in[2];
    // d_in[3] = position_ids (arange(L); not dereferenced — dtype ambiguous)
    // d_in[4] = seq_len (compile-time constant L here)
    const float* kc_in = (const float*)d_in[5];
    const float* vc_in = (const float*)d_in[6];
    const float* lnw = (const float*)d_in[7];
    const float* Wq = (const float*)d_in[8];
    const float* Wk = (const float*)d_in[9];
    const float* Wv = (const float*)d_in[10];
    const float* Wo = (const float*)d_in[11];

    float* out = (float*)d_out;
    float* kc_out = out + (size_t)L * HID;
    float* vc_out = kc_out + (size_t)MAXP * NKV * HD;

    float *pH, *pQ, *pK, *pV, *pA;
    cudaGetSymbolAddress((void**)&pH, g_h);
    cudaGetSymbolAddress((void**)&pQ, g_q);
    cudaGetSymbolAddress((void**)&pK, g_k);
    cudaGetSymbolAddress((void**)&pV, g_v);
    cudaGetSymbolAddress((void**)&pA, g_attn);

    copy_caches_kernel<<<(2 * MAXP * NKV * HD / 4) / 256, 256>>>(
        (const float4*)kc_in, (const float4*)vc_in, (float4*)kc_out, (float4*)vc_out);

    rmsnorm_kernel<<<L, 256>>>(x, lnw);

    gemm_nt_kernel<false><<<dim3(HID / 128, L / 128), 256>>>(pH, Wq, pQ, HID, nullptr);
    gemm_nt_kernel<false><<<dim3((NKV * HD) / 128, L / 128), 256>>>(pH, Wk, pK, NKV * HD, nullptr);
    gemm_nt_kernel<false><<<dim3((NKV * HD) / 128, L / 128), 256>>>(pH, Wv, pV, NKV * HD, nullptr);

    rope_q_kernel<<<(L * NH * 64) / 256, 256>>>(cosb, sinb);
    rope_kv_kernel<<<(L * NKV * 64) / 256, 256>>>(cosb, sinb, kc_out, vc_out);

    const int flash_smem = (3 * 64 * 128 + 64 * PS_STRIDE) * 4;  // 115712
    cudaFuncSetAttribute(flash_kernel, cudaFuncAttributeMaxDynamicSharedMemorySize, flash_smem);
    flash_kernel<<<dim3(L / 64, NH), 256, flash_smem>>>(pQ, pK, pV, pA);

    gemm_nt_kernel<true><<<dim3(HID / 128, L / 128), 256>>>(pA, Wo, out, HID, x);
}

// round 5
// speedup vs baseline: 2.9231x; 2.9231x over previous
#include <cuda_runtime.h>
#include <cuda_bf16.h>
#include <cstdint>

#define L 2048
#define HID 4096
#define NH 32
#define NKV 8
#define HD 128
#define MAXP 4096

// ---------------------------------------------------------------------------
// PTX helpers (sm_80-class instructions only: valid on baseline sm_103 target)
// ---------------------------------------------------------------------------
__device__ __forceinline__ uint32_t smem_u32(const void* p) {
    uint32_t a;
    asm("{ .reg .u64 t; cvta.to.shared.u64 t, %1; cvt.u32.u64 %0, t; }" : "=r"(a) : "l"(p));
    return a;
}
__device__ __forceinline__ float fast_exp2(float x) {
    float y;
    asm("ex2.approx.f32 %0, %1;" : "=f"(y) : "f"(x));
    return y;
}
#define LDSM_X4(r0, r1, r2, r3, addr)                                              \
    asm volatile("ldmatrix.sync.aligned.m8n8.x4.shared.b16 {%0,%1,%2,%3}, [%4];"   \
                 : "=r"(r0), "=r"(r1), "=r"(r2), "=r"(r3) : "r"(addr))
#define LDSM_X4_T(r0, r1, r2, r3, addr)                                            \
    asm volatile("ldmatrix.sync.aligned.m8n8.x4.trans.shared.b16 {%0,%1,%2,%3}, [%4];" \
                 : "=r"(r0), "=r"(r1), "=r"(r2), "=r"(r3) : "r"(addr))
#define MMA_BF16(d, a, b)                                                          \
    asm volatile("mma.sync.aligned.m16n8k16.row.col.f32.bf16.bf16.f32 "            \
                 "{%0,%1,%2,%3}, {%4,%5,%6,%7}, {%8,%9}, {%0,%1,%2,%3};"           \
                 : "+f"((d)[0]), "+f"((d)[1]), "+f"((d)[2]), "+f"((d)[3])          \
                 : "r"((a)[0]), "r"((a)[1]), "r"((a)[2]), "r"((a)[3]),             \
                   "r"((b)[0]), "r"((b)[1]))
#define CP_ASYNC16(dst, src)                                                       \
    asm volatile("cp.async.cg.shared.global [%0], [%1], 16;" :: "r"(dst), "l"(src))
#define CP_COMMIT() asm volatile("cp.async.commit_group;" ::: "memory")
#define CP_WAIT(n) asm volatile("cp.async.wait_group %0;" :: "n"(n) : "memory")

// ---------------------------------------------------------------------------
// scratch (device globals; no runtime alloc)
// ---------------------------------------------------------------------------
#define NW_TOTAL 41943040
#define OFF_WQ 0
#define OFF_WK 16777216
#define OFF_WV 20971520
#define OFF_WO 25165824

__device__ __nv_bfloat16 g_h_hi[(size_t)L * HID];
__device__ __nv_bfloat16 g_h_lo[(size_t)L * HID];
__device__ __nv_bfloat16 g_w_hi[(size_t)NW_TOTAL];
__device__ __nv_bfloat16 g_w_lo[(size_t)NW_TOTAL];
__device__ __nv_bfloat16 g_a_hi[(size_t)L * HID];
__device__ __nv_bfloat16 g_a_lo[(size_t)L * HID];
__device__ __nv_bfloat16 g_qh[(size_t)L * HID];
__device__ __nv_bfloat16 g_ql[(size_t)L * HID];
__device__ __nv_bfloat16 g_kh[(size_t)L * NKV * HD];
__device__ __nv_bfloat16 g_kl[(size_t)L * NKV * HD];
__device__ __nv_bfloat16 g_vb[(size_t)L * NKV * HD];
__device__ float g_q[(size_t)L * HID];
__device__ float g_k[(size_t)L * NKV * HD];
__device__ float g_v[(size_t)L * NKV * HD];

__device__ __forceinline__ void split_bf16(float x, __nv_bfloat16& hi, __nv_bfloat16& lo) {
    hi = __float2bfloat16_rn(x);
    lo = __float2bfloat16_rn(x - __bfloat162float(hi));
}
__device__ __forceinline__ uint32_t pack_bf16(float lo, float hi) {
    __nv_bfloat162 t = __floats2bfloat162_rn(lo, hi);  // .x = lo bits [15:0]
    return *(uint32_t*)&t;
}

// ---------------------------------------------------------------------------
// cache copy
// ---------------------------------------------------------------------------
__global__ void copy_caches_kernel(const float4* __restrict__ kin,
                                   const float4* __restrict__ vin,
                                   float4* __restrict__ kout,
                                   float4* __restrict__ vout) {
    int idx = blockIdx.x * 256 + threadIdx.x;
    const int n4 = MAXP * NKV * HD / 4;
    if (idx < n4) kout[idx] = kin[idx];
    else vout[idx - n4] = vin[idx - n4];
}

// ---------------------------------------------------------------------------
// weight split-convert
// ---------------------------------------------------------------------------
__global__ void convert_split_kernel(const float4* __restrict__ src,
                                     __nv_bfloat16* __restrict__ hi,
                                     __nv_bfloat16* __restrict__ lo, int n4) {
    int i = blockIdx.x * 256 + threadIdx.x;
    if (i >= n4) return;
    float4 v = src[i];
    __nv_bfloat16 h0, h1, h2, h3, l0, l1, l2, l3;
    split_bf16(v.x, h0, l0); split_bf16(v.y, h1, l1);
    split_bf16(v.z, h2, l2); split_bf16(v.w, h3, l3);
    __nv_bfloat162* hp = (__nv_bfloat162*)(hi + (size_t)i * 4);
    __nv_bfloat162* lp = (__nv_bfloat162*)(lo + (size_t)i * 4);
    hp[0] = __nv_bfloat162(h0, h1); hp[1] = __nv_bfloat162(h2, h3);
    lp[0] = __nv_bfloat162(l0, l1); lp[1] = __nv_bfloat162(l2, l3);
}

// ---------------------------------------------------------------------------
// RMSNorm -> split bf16
// ---------------------------------------------------------------------------
__global__ void __launch_bounds__(256) rmsnorm_kernel(const float* __restrict__ x,
                                                      const float* __restrict__ w) {
    int row = blockIdx.x;
    const float* xr = x + (size_t)row * HID;
    int t = threadIdx.x;
    float vals[16];
    float local = 0.f;
#pragma unroll
    for (int i = 0; i < 16; ++i) {
        float v = xr[t + i * 256];
        vals[i] = v;
        local += v * v;
    }
    __shared__ float red[8];
#pragma unroll
    for (int o = 16; o; o >>= 1) local += __shfl_xor_sync(0xffffffffu, local, o);
    if ((t & 31) == 0) red[t >> 5] = local;
    __syncthreads();
    if (t < 8) {
        float v = red[t];
#pragma unroll
        for (int o = 4; o; o >>= 1) v += __shfl_xor_sync(0xffu, v, o);
        if (t == 0) red[0] = v;
    }
    __syncthreads();
    float rms = rsqrtf(red[0] / (float)HID + 1e-5f);
    size_t base = (size_t)row * HID;
#pragma unroll
    for (int i = 0; i < 16; ++i) {
        float y = vals[i] * rms * w[t + i * 256];
        __nv_bfloat16 h, l;
        split_bf16(y, h, l);
        g_h_hi[base + t + i * 256] = h;
        g_h_lo[base + t + i * 256] = l;
    }
}

// ---------------------------------------------------------------------------
// split-bf16 GEMM via mma.sync: C[M,N] = A[M,K] B[N,K]^T (+res), K=4096
// CTA 128x128, 8 warps (2x4), warp tile 64x32, K-chunk 64, cp.async 2-stage.
// ---------------------------------------------------------------------------
#define GSTRIDE 144
#define GTILE 18432   // 128 * 144
#define GSTAGE 73728  // 4 tiles
#define GEMM_SMEM (2 * GSTAGE)

template <bool ADD_RES>
__global__ void __launch_bounds__(256, 1) mma_gemm_kernel(
    const __nv_bfloat16* __restrict__ Ah, const __nv_bfloat16* __restrict__ Al,
    const __nv_bfloat16* __restrict__ Bh, const __nv_bfloat16* __restrict__ Bl,
    float* __restrict__ C, int N, const float* __restrict__ res) {
    extern __shared__ char sm[];
    const uint32_t sb = smem_u32(sm);
    const int tid = threadIdx.x;
    const int lane = tid & 31, w = tid >> 5;
    const int wm = w >> 2, wn = w & 3;
    const int bm = blockIdx.y * 128, bn = blockIdx.x * 128;

    float acc[4][4][4];
#pragma unroll
    for (int a = 0; a < 4; ++a)
#pragma unroll
        for (int b = 0; b < 4; ++b)
#pragma unroll
            for (int c = 0; c < 4; ++c) acc[a][b][c] = 0.f;

    const __nv_bfloat16* srcs[4] = {Ah, Al, Bh, Bl};

    auto issue = [&](int c, int s) {
#pragma unroll
        for (int j = 0; j < 16; ++j) {
            const int t = j >> 2;
            const int local = tid + (j & 3) * 256;
            const int row = local >> 3;
            const int seg = local & 7;
            const int grow = (t < 2 ? bm : bn) + row;
            const void* g = srcs[t] + (size_t)grow * HID + c * 64 + seg * 8;
            uint32_t dst = sb + s * GSTAGE + t * GTILE + row * GSTRIDE + seg * 16;
            CP_ASYNC16(dst, g);
        }
    };

    auto compute = [&](int s) {
        const uint32_t base = sb + s * GSTAGE;
        const int rsel = lane & 15;
        const int csel = (lane >> 4) << 4;
#pragma unroll
        for (int ks = 0; ks < 4; ++ks) {
            uint32_t ah[4][4], al[4][4];
#pragma unroll
            for (int mt = 0; mt < 4; ++mt) {
                uint32_t ad = base + (wm * 64 + mt * 16 + rsel) * GSTRIDE + ks * 32 + csel;
                LDSM_X4(ah[mt][0], ah[mt][1], ah[mt][2], ah[mt][3], ad);
                LDSM_X4(al[mt][0], al[mt][1], al[mt][2], al[mt][3], ad + GTILE);
            }
            uint32_t bh[4][2], bl[4][2];
#pragma unroll
            for (int g = 0; g < 2; ++g) {
                uint32_t bd = base + 2 * GTILE + (wn * 32 + g * 16 + rsel) * GSTRIDE + ks * 32 + csel;
                uint32_t t0, t1, t2, t3;
                LDSM_X4(t0, t1, t2, t3, bd);
                bh[2 * g][0] = t0; bh[2 * g][1] = t2;
                bh[2 * g + 1][0] = t1; bh[2 * g + 1][1] = t3;
                LDSM_X4(t0, t1, t2, t3, bd + GTILE);
                bl[2 * g][0] = t0; bl[2 * g][1] = t2;
                bl[2 * g + 1][0] = t1; bl[2 * g + 1][1] = t3;
            }
#pragma unroll
            for (int mt = 0; mt < 4; ++mt)
#pragma unroll
                for (int nt = 0; nt < 4; ++nt) {
                    MMA_BF16(acc[mt][nt], ah[mt], bh[nt]);
                    MMA_BF16(acc[mt][nt], ah[mt], bl[nt]);
                    MMA_BF16(acc[mt][nt], al[mt], bh[nt]);
                }
        }
    };

    issue(0, 0);
    CP_COMMIT();
#pragma unroll 1
    for (int c = 0; c < 64; ++c) {
        __syncthreads();
        if (c + 1 < 64) {
            issue(c + 1, (c + 1) & 1);
            CP_COMMIT();
            CP_WAIT(1);
        } else {
            CP_WAIT(0);
        }
        __syncthreads();
        compute(c & 1);
    }

#pragma unroll
    for (int mt = 0; mt < 4; ++mt)
#pragma unroll
        for (int nt = 0; nt < 4; ++nt) {
            int row = bm + wm * 64 + mt * 16 + (lane >> 2);
            int col = bn + wn * 32 + nt * 8 + ((lane & 3) << 1);
            size_t o0 = (size_t)row * N + col;
            size_t o1 = (size_t)(row + 8) * N + col;
            float2 v0 = make_float2(acc[mt][nt][0], acc[mt][nt][1]);
            float2 v1 = make_float2(acc[mt][nt][2], acc[mt][nt][3]);
            if (ADD_RES) {
                float2 r0 = *(const float2*)&res[o0];
                float2 r1 = *(const float2*)&res[o1];
                v0.x += r0.x; v0.y += r0.y;
                v1.x += r1.x; v1.y += r1.y;
            }
            *(float2*)&C[o0] = v0;
            *(float2*)&C[o1] = v1;
        }
}

// ---------------------------------------------------------------------------
// RoPE Q: fp32 in g_q -> scaled (1/sqrt(hd) * log2e) split bf16
// ---------------------------------------------------------------------------
__global__ void rope_q_kernel(const float* __restrict__ cosb, const float* __restrict__ sinb) {
    const float QS = 0.08838834764831845f * 1.4426950408889634f;
    int idx = blockIdx.x * 256 + threadIdx.x;
    int d = idx & 63;
    int h = (idx >> 6) & (NH - 1);
    int i = idx >> 11;
    const float* qp = g_q + (size_t)i * HID + h * HD;
    float c0 = cosb[i * HD + d], s0 = sinb[i * HD + d];
    float c1 = cosb[i * HD + d + 64], s1 = sinb[i * HD + d + 64];
    float q0 = qp[d], q1 = qp[d + 64];
    float r0 = (q0 * c0 - q1 * s0) * QS;
    float r1 = (q1 * c1 + q0 * s1) * QS;
    size_t base = (size_t)i * HID + h * HD;
    __nv_bfloat16 hh, ll;
    split_bf16(r0, hh, ll);
    g_qh[base + d] = hh; g_ql[base + d] = ll;
    split_bf16(r1, hh, ll);
    g_qh[base + d + 64] = hh; g_ql[base + d + 64] = ll;
}

// RoPE K + scatter fp32 caches + split bf16 K, bf16 V (position = row index)
__global__ void rope_kv_kernel(const float* __restrict__ cosb, const float* __restrict__ sinb,
                               float* __restrict__ kc_out, float* __restrict__ vc_out) {
    int idx = blockIdx.x * 256 + threadIdx.x;
    int d = idx & 63;
    int h = (idx >> 6) & (NKV - 1);
    int i = idx >> 9;
    size_t base = (size_t)i * (NKV * HD) + h * HD;
    float c0 = cosb[i * HD + d], s0 = sinb[i * HD + d];
    float c1 = cosb[i * HD + d + 64], s1 = sinb[i * HD + d + 64];
    float k0 = g_k[base + d], k1 = g_k[base + d + 64];
    float k0n = k0 * c0 - k1 * s0;
    float k1n = k1 * c1 + k0 * s1;
    kc_out[base + d] = k0n;
    kc_out[base + d + 64] = k1n;
    __nv_bfloat16 hh, ll;
    split_bf16(k0n, hh, ll);
    g_kh[base + d] = hh; g_kl[base + d] = ll;
    split_bf16(k1n, hh, ll);
    g_kh[base + d + 64] = hh; g_kl[base + d + 64] = ll;
    float v0 = g_v[base + d], v1 = g_v[base + d + 64];
    vc_out[base + d] = v0;
    vc_out[base + d + 64] = v1;
    g_vb[base + d] = __float2bfloat16_rn(v0);
    g_vb[base + d + 64] = __float2bfloat16_rn(v1);
}

// ---------------------------------------------------------------------------
// Flash attention via mma.sync: BM=128 (8 warps x m16), BN=64, HD=128.
// QK^T split bf16 (3 mma terms); softmax fp32 (exp2, scale folded into Q);
// P bf16 register-reuse; PV bf16 via ldmatrix.trans on V.
// ---------------------------------------------------------------------------
#define FSTRIDE 272
#define FQH 0
#define FQL 34816
#define FKH 69632
#define FKL 87040
#define FV 104448
#define FLASH_SMEM 121856

__global__ void __launch_bounds__(256, 1) flash_kernel() {
    extern __shared__ char sm[];
    const uint32_t sb = smem_u32(sm);
    const int tid = threadIdx.x;
    const int lane = tid & 31, w = tid >> 5;
    const int qt = blockIdx.x, head = blockIdx.y;
    const int kvh = head >> 2;
    const int rsel = lane & 15;
    const int csel = (lane >> 4) << 4;

    // Q tiles (hi, lo): 128 x 128 bf16 each
#pragma unroll
    for (int j = 0; j < 16; ++j) {
        const int term = j >> 3;
        const int local = tid + (j & 7) * 256;
        const int row = local >> 4;
        const int seg = local & 15;
        const __nv_bfloat16* src = (term ? g_ql : g_qh);
        const void* g = src + (size_t)(qt * 128 + row) * HID + head * HD + seg * 8;
        uint32_t dst = sb + (term ? FQL : FQH) + row * FSTRIDE + seg * 16;
        CP_ASYNC16(dst, g);
    }
    CP_COMMIT();

    float o_[16][4];
#pragma unroll
    for (int n = 0; n < 16; ++n)
#pragma unroll
        for (int c = 0; c < 4; ++c) o_[n][c] = 0.f;
    float m_[2] = {-1e30f, -1e30f};
    float l_[2] = {0.f, 0.f};

    const int kt_end = 2 * qt + 2;
#pragma unroll 1
    for (int kt = 0; kt < kt_end; ++kt) {
        __syncthreads();
#pragma unroll
        for (int j = 0; j < 12; ++j) {
            const int t = j >> 2;
            const int local = tid + (j & 3) * 256;
            const int row = local >> 4;
            const int seg = local & 15;
            const __nv_bfloat16* src = (t == 0) ? g_kh : (t == 1) ? g_kl : g_vb;
            const void* g = src + (size_t)(kt * 64 + row) * (NKV * HD) + kvh * HD + seg * 8;
            uint32_t dst = sb + ((t == 0) ? FKH : (t == 1) ? FKL : FV) + row * FSTRIDE + seg * 16;
            CP_ASYNC16(dst, g);
        }
        CP_COMMIT();
        CP_WAIT(0);
        __syncthreads();

        // S = Q' K^T (3-term split), acc in log2-units (scale folded into Q)
        float s[8][4];
#pragma unroll
        for (int n = 0; n < 8; ++n)
#pragma unroll
            for (int c = 0; c < 4; ++c) s[n][c] = 0.f;
#pragma unroll
        for (int ks = 0; ks < 8; ++ks) {
            uint32_t ah[4], al[4];
            uint32_t aaddr = sb + FQH + (w * 16 + rsel) * FSTRIDE + ks * 32 + csel;
            LDSM_X4(ah[0], ah[1], ah[2], ah[3], aaddr);
            LDSM_X4(al[0], al[1], al[2], al[3], aaddr + (FQL - FQH));
#pragma unroll
            for (int g = 0; g < 4; ++g) {
                uint32_t bd = sb + FKH + (g * 16 + rsel) * FSTRIDE + ks * 32 + csel;
                uint32_t t0, t1, t2, t3;
                uint32_t bh0[2], bh1[2], bl0[2], bl1[2];
                LDSM_X4(t0, t1, t2, t3, bd);
                bh0[0] = t0; bh0[1] = t2; bh1[0] = t1; bh1[1] = t3;
                LDSM_X4(t0, t1, t2, t3, bd + (FKL - FKH));
                bl0[0] = t0; bl0[1] = t2; bl1[0] = t1; bl1[1] = t3;
                MMA_BF16(s[2 * g], ah, bh0);
                MMA_BF16(s[2 * g], ah, bl0);
                MMA_BF16(s[2 * g], al, bh0);
                MMA_BF16(s[2 * g + 1], ah, bh1);
                MMA_BF16(s[2 * g + 1], ah, bl1);
                MMA_BF16(s[2 * g + 1], al, bh1);
            }
        }

        // causal mask (only the top-two kv tiles can cross the diagonal)
        if (kt >= 2 * qt) {
            const int r0g = qt * 128 + w * 16 + (lane >> 2);
#pragma unroll
            for (int j = 0; j < 8; ++j) {
                int cb = kt * 64 + j * 8 + ((lane & 3) << 1);
                if (cb > r0g) s[j][0] = -1e30f;
                if (cb + 1 > r0g) s[j][1] = -1e30f;
                if (cb > r0g + 8) s[j][2] = -1e30f;
                if (cb + 1 > r0g + 8) s[j][3] = -1e30f;
            }
        }

        // online softmax per row-half
#pragma unroll
        for (int i = 0; i < 2; ++i) {
            float mt_ = -1e30f;
#pragma unroll
            for (int j = 0; j < 8; ++j)
                mt_ = fmaxf(mt_, fmaxf(s[j][2 * i], s[j][2 * i + 1]));
            mt_ = fmaxf(mt_, __shfl_xor_sync(0xffffffffu, mt_, 1));
            mt_ = fmaxf(mt_, __shfl_xor_sync(0xffffffffu, mt_, 2));
            float mn = fmaxf(m_[i], mt_);
            float corr = fast_exp2(m_[i] - mn);
            m_[i] = mn;
            float rs = 0.f;
#pragma unroll
            for (int j = 0; j < 8; ++j) {
                float p0 = fast_exp2(s[j][2 * i] - mn);
                float p1 = fast_exp2(s[j][2 * i + 1] - mn);
                s[j][2 * i] = p0;
                s[j][2 * i + 1] = p1;
                rs += p0 + p1;
            }
            rs += __shfl_xor_sync(0xffffffffu, rs, 1);
            rs += __shfl_xor_sync(0xffffffffu, rs, 2);
            l_[i] = l_[i] * corr + rs;
#pragma unroll
            for (int n = 0; n < 16; ++n) {
                o_[n][2 * i] *= corr;
                o_[n][2 * i + 1] *= corr;
            }
        }

        // P -> A fragments (FA2 register identity)
        uint32_t pa[4][4];
#pragma unroll
        for (int t = 0; t < 4; ++t) {
            pa[t][0] = pack_bf16(s[2 * t][0], s[2 * t][1]);
            pa[t][1] = pack_bf16(s[2 * t][2], s[2 * t][3]);
            pa[t][2] = pack_bf16(s[2 * t + 1][0], s[2 * t + 1][1]);
            pa[t][3] = pack_bf16(s[2 * t + 1][2], s[2 * t + 1][3]);
        }

        // O += P V  (V^T fragments via ldmatrix.trans)
#pragma unroll
        for (int t = 0; t < 4; ++t) {
#pragma unroll
            for (int g = 0; g < 8; ++g) {
                uint32_t vaddr = sb + FV + (t * 16 + rsel) * FSTRIDE +
                                 (g * 16 + ((lane >> 4) << 3)) * 2;
                uint32_t t0, t1, t2, t3;
                LDSM_X4_T(t0, t1, t2, t3, vaddr);
                uint32_t b0[2] = {t0, t1}, b1[2] = {t2, t3};
                MMA_BF16(o_[2 * g], pa[t], b0);
                MMA_BF16(o_[2 * g + 1], pa[t], b1);
            }
        }
    }

    // epilogue: normalize and emit split bf16 attention output
    const float inv0 = 1.f / l_[0];
    const float inv1 = 1.f / l_[1];
    const int r0g = qt * 128 + w * 16 + (lane >> 2);
#pragma unroll
    for (int nt = 0; nt < 16; ++nt) {
        int col = head * HD + nt * 8 + ((lane & 3) << 1);
        size_t o0 = (size_t)r0g * HID + col;
        size_t o1 = o0 + (size_t)8 * HID;
        __nv_bfloat16 h0, l0, h1, l1;
        split_bf16(o_[nt][0] * inv0, h0, l0);
        split_bf16(o_[nt][1] * inv0, h1, l1);
        *(__nv_bfloat162*)(g_a_hi + o0) = __nv_bfloat162(h0, h1);
        *(__nv_bfloat162*)(g_a_lo + o0) = __nv_bfloat162(l0, l1);
        split_bf16(o_[nt][2] * inv1, h0, l0);
        split_bf16(o_[nt][3] * inv1, h1, l1);
        *(__nv_bfloat162*)(g_a_hi + o1) = __nv_bfloat162(h0, h1);
        *(__nv_bfloat162*)(g_a_lo + o1) = __nv_bfloat162(l0, l1);
    }
}

// ---------------------------------------------------------------------------
// launch
// ---------------------------------------------------------------------------
extern "C" void kernel_launch(void* const* d_in, const int* in_sizes, int n_in,
                              void* d_out, int out_size) {
    const float* x = (const float*)d_in[0];
    const float* cosb = (const float*)d_in[1];
    const float* sinb = (const float*)d_in[2];
    // d_in[3] position_ids (arange; not dereferenced), d_in[4] seq_len
    const float* kc_in = (const float*)d_in[5];
    const float* vc_in = (const float*)d_in[6];
    const float* lnw = (const float*)d_in[7];
    const float* Wq = (const float*)d_in[8];
    const float* Wk = (const float*)d_in[9];
    const float* Wv = (const float*)d_in[10];
    const float* Wo = (const float*)d_in[11];

    float* out = (float*)d_out;
    float* kc_out = out + (size_t)L * HID;
    float* vc_out = kc_out + (size_t)MAXP * NKV * HD;

    __nv_bfloat16 *pHh, *pHl, *pWh, *pWl, *pAh, *pAl;
    float *pQ, *pK, *pV;
    cudaGetSymbolAddress((void**)&pHh, g_h_hi);
    cudaGetSymbolAddress((void**)&pHl, g_h_lo);
    cudaGetSymbolAddress((void**)&pWh, g_w_hi);
    cudaGetSymbolAddress((void**)&pWl, g_w_lo);
    cudaGetSymbolAddress((void**)&pAh, g_a_hi);
    cudaGetSymbolAddress((void**)&pAl, g_a_lo);
    cudaGetSymbolAddress((void**)&pQ, g_q);
    cudaGetSymbolAddress((void**)&pK, g_k);
    cudaGetSymbolAddress((void**)&pV, g_v);

    copy_caches_kernel<<<(2 * MAXP * NKV * HD / 4) / 256, 256>>>(
        (const float4*)kc_in, (const float4*)vc_in, (float4*)kc_out, (float4*)vc_out);

    convert_split_kernel<<<(OFF_WK / 4) / 256, 256>>>((const float4*)Wq, pWh + OFF_WQ, pWl + OFF_WQ, OFF_WK / 4);
    convert_split_kernel<<<((OFF_WV - OFF_WK) / 4) / 256, 256>>>((const float4*)Wk, pWh + OFF_WK, pWl + OFF_WK, (OFF_WV - OFF_WK) / 4);
    convert_split_kernel<<<((OFF_WO - OFF_WV) / 4) / 256, 256>>>((const float4*)Wv, pWh + OFF_WV, pWl + OFF_WV, (OFF_WO - OFF_WV) / 4);
    convert_split_kernel<<<((NW_TOTAL - OFF_WO) / 4) / 256, 256>>>((const float4*)Wo, pWh + OFF_WO, pWl + OFF_WO, (NW_TOTAL - OFF_WO) / 4);

    rmsnorm_kernel<<<L, 256>>>(x, lnw);

    cudaFuncSetAttribute(mma_gemm_kernel<false>, cudaFuncAttributeMaxDynamicSharedMemorySize, GEMM_SMEM);
    cudaFuncSetAttribute(mma_gemm_kernel<true>, cudaFuncAttributeMaxDynamicSharedMemorySize, GEMM_SMEM);

    mma_gemm_kernel<false><<<dim3(HID / 128, L / 128), 256, GEMM_SMEM>>>(
        pHh, pHl, pWh + OFF_WQ, pWl + OFF_WQ, pQ, HID, nullptr);
    mma_gemm_kernel<false><<<dim3((NKV * HD) / 128, L / 128), 256, GEMM_SMEM>>>(
        pHh, pHl, pWh + OFF_WK, pWl + OFF_WK, pK, NKV * HD, nullptr);
    mma_gemm_kernel<false><<<dim3((NKV * HD) / 128, L / 128), 256, GEMM_SMEM>>>(
        pHh, pHl, pWh + OFF_WV, pWl + OFF_WV, pV, NKV * HD, nullptr);

    rope_q_kernel<<<(L * NH * 64) / 256, 256>>>(cosb, sinb);
    rope_kv_kernel<<<(L * NKV * 64) / 256, 256>>>(cosb, sinb, kc_out, vc_out);

    cudaFuncSetAttribute(flash_kernel, cudaFuncAttributeMaxDynamicSharedMemorySize, FLASH_SMEM);
    flash_kernel<<<dim3(L / 128, NH), 256, FLASH_SMEM>>>();

    mma_gemm_kernel<true><<<dim3(HID / 128, L / 128), 256, GEMM_SMEM>>>(
        pAh, pAl, pWh + OFF_WO, pWl + OFF_WO, out, HID, x);
}